// round 8
// baseline (speedup 1.0000x reference)
#include <cuda_runtime.h>
#include <cuda_fp16.h>
#include <math.h>
#include <stdint.h>

#define NB   16384
#define HID  256
#define TOUT 16
#define MSPLIT 9
#define AW 20

// ---------------- persistent device scratch ----------------
__device__ float  d_W4h[4][1024 * 256];   // permuted recurrent weights [col'][k] (fp32)
__device__ float  d_W4i[4][1024 * 4];
__device__ float  d_b4 [4][1024];
__device__ __half d_hbuf[4][2][NB * HID]; // hidden state, fp16
__device__ float  d_cbuf[4][NB * HID];    // cell state, fp32
__device__ float  d_xs[NB * 4];
__device__ float  d_xc[NB * 4];

__device__ __forceinline__ float sigf(float x) { return 1.0f / (1.0f + expf(-x)); }
__device__ __forceinline__ float sig_fast(float x) {
    float e = __expf(-x);
    return __fdividef(1.0f, 1.0f + e);
}
__device__ __forceinline__ float tanh_fast(float x) {
    float e = __expf(-2.0f * x);
    return (1.0f - e) * __fdividef(1.0f, 1.0f + e);
}
__device__ __forceinline__ float gclamp(float x) { return fminf(fmaxf(x, -30.0f), 30.0f); }

__device__ __forceinline__ void mma_f16acc(uint32_t* d,
    uint32_t a0, uint32_t a1, uint32_t a2, uint32_t a3, uint32_t b0, uint32_t b1) {
    asm volatile("mma.sync.aligned.m16n8k16.row.col.f16.f16.f16.f16 "
        "{%0,%1}, {%2,%3,%4,%5}, {%6,%7}, {%0,%1};"
        : "+r"(d[0]), "+r"(d[1])
        : "r"(a0), "r"(a1), "r"(a2), "r"(a3), "r"(b0), "r"(b1));
}

__device__ __forceinline__ __half2 H2(uint32_t u) { return *(__half2*)&u; }
__device__ __forceinline__ uint2 ld2(const __half* p) { return *(const uint2*)p; }
__device__ __forceinline__ uint2 add2(uint2 a, uint2 b) {
    __half2 ax = __hadd2(H2(a.x), H2(b.x));
    __half2 ay = __hadd2(H2(a.y), H2(b.y));
    uint2 r; r.x = *(uint32_t*)&ax; r.y = *(uint32_t*)&ay; return r;
}

// ---------------- SMEM layout (bytes) ----------------
#define SM_WI   0                        // 128*4 floats = 2048
#define SM_BI   2048                     // 512
#define SM_B    2560                     // 8*128*AW*4 = 81920
#define SM_TOTAL (2560 + 8 * 128 * AW * 4)

// ---------------- weight permutation ----------------
__global__ void prep_kernel(int cell,
                            const float* __restrict__ Whh,
                            const float* __restrict__ Wih,
                            const float* __restrict__ bih,
                            const float* __restrict__ bhh) {
    int colp = blockIdx.x;
    int k    = threadIdx.x;
    int g    = (colp & 127) >> 5;
    int u    = ((colp >> 7) << 5) + (colp & 31);
    int orig = g * 256 + u;
    d_W4h[cell][colp * 256 + k] = Whh[orig * 256 + k];
    if (k < 4) d_W4i[cell][colp * 4 + k] = Wih[orig * 4 + k];
    if (k == 0) d_b4[cell][colp] = bih[orig] + bhh[orig];
}

// ---------------- first step (h=c=0) ----------------
__global__ __launch_bounds__(256, 2) void cell_first_kernel(
    const float* __restrict__ x0, const float* __restrict__ x1, int xstride)
{
    int cell = blockIdx.z;
    const float* x = blockIdx.z == 0 ? x0 : x1;
    __half* hout = d_hbuf[cell][1];
    float*  cout = d_cbuf[cell];
    int row0 = blockIdx.y << 7;
    int col0 = blockIdx.x << 7;
    int tx = threadIdx.x & 15;
    int ty = threadIdx.x >> 4;

    float xv[8][4];
    #pragma unroll
    for (int rr = 0; rr < 8; rr++) {
        int row = row0 + (ty << 3) + rr;
        #pragma unroll
        for (int s = 0; s < 4; s++) xv[rr][s] = x[(size_t)row * xstride + s];
    }
    const float* Wi = d_W4i[cell];
    const float* bb = d_b4[cell];
    int ubase = blockIdx.x << 5;

    #pragma unroll
    for (int hh = 0; hh < 2; hh++) {
        int u = ubase + tx + (hh << 4);
        float wi[4][4], bg[4];
        #pragma unroll
        for (int g = 0; g < 4; g++) {
            int colp = col0 + (g << 5) + tx + (hh << 4);
            bg[g] = bb[colp];
            #pragma unroll
            for (int s = 0; s < 4; s++) wi[g][s] = Wi[colp * 4 + s];
        }
        #pragma unroll
        for (int rr = 0; rr < 8; rr++) {
            int row = row0 + (ty << 3) + rr;
            float gt[4];
            #pragma unroll
            for (int g = 0; g < 4; g++) {
                float v = bg[g];
                #pragma unroll
                for (int s = 0; s < 4; s++) v = fmaf(wi[g][s], xv[rr][s], v);
                gt[g] = v;
            }
            float ig = sigf(gt[0]);
            float gg = tanhf(gt[2]);
            float og = sigf(gt[3]);
            float cn = ig * gg;
            float hn = og * tanhf(cn);
            cout[(size_t)row * HID + u] = cn;
            hout[(size_t)row * HID + u] = __float2half(hn);
        }
    }
}

// ---------------- hybrid tensor+fma LSTM step ----------------
// block 384 = 8 mma warps (u 0-23) + 4 fma warps (u 24-31). Barrier-free mainloop.
// B SMEM k-permuted per 16-half block: word w<4 holds phys halfs {4w,4w+1};
// word w>=4 holds {4(w-4)+2, 4(w-4)+3}. A fragments use the same permutation.
__global__ __launch_bounds__(384, 1) void cell_mma_kernel(
    int cell_base, const float* __restrict__ x0, const float* __restrict__ x1,
    int xstride, int rd, int use_comb, int use_fb)
{
    extern __shared__ char smem[];
    float* smWI = (float*)(smem + SM_WI);
    float* smBI = (float*)(smem + SM_BI);
    uint32_t* smB = (uint32_t*)(smem + SM_B);   // [8][128][AW]

    int tid = threadIdx.x;
    int wid = tid >> 5, lane = tid & 31;
    int gid = lane >> 2, tig = lane & 3;
    int cell = cell_base + blockIdx.y;
    const float* x = use_fb ? (blockIdx.y == 0 ? d_xs : d_xc)
                            : (blockIdx.y == 0 ? x0 : x1);
    const __half* hin  = use_comb ? d_hbuf[0][0] : d_hbuf[cell][rd];
    const __half* hin2 = d_hbuf[1][0];
    const float*  cin  = use_comb ? d_cbuf[0] : d_cbuf[cell];
    const float*  cin2 = d_cbuf[1];
    __half* hout = d_hbuf[cell][rd ^ 1];
    float*  cout = d_cbuf[cell];
    const float* Wh = d_W4h[cell];
    int nt = blockIdx.x;
    int col0 = nt << 7;
    int m_lo = (blockIdx.z * 128) / MSPLIT;
    int m_hi = ((blockIdx.z + 1) * 128) / MSPLIT;

    // ---- B fill (threads 0..255), k-permuted fp16; Wi, bias ----
    if (tid < 256) {
        int r = tid >> 1, s = tid & 1;
        const float* wrow = Wh + (size_t)(col0 + r) * 256;
        for (int c = 0; c < 8; c++) {
            uint32_t* dst = smB + ((size_t)c * 128 + r) * AW + s * 8;
            #pragma unroll
            for (int w = 0; w < 8; w++) {
                int q = (w < 4) ? 4 * w : 4 * (w - 4) + 2;
                float2 v = *(const float2*)(wrow + c * 32 + s * 16 + q);
                __half2 h2 = __floats2half2_rn(v.x, v.y);
                dst[w] = *(uint32_t*)&h2;
            }
        }
        if (tid < 128)
            *(float4*)(smWI + tid * 4) = *(const float4*)(d_W4i[cell] + (size_t)(col0 + tid) * 4);
        if (tid < 32)
            *(float4*)(smBI + tid * 4) = *(const float4*)(d_b4[cell] + col0 + tid * 4);
    }
    __syncthreads();

    if (wid < 8) {
        // ============ tensor warps: rows wid*16 + gid (+8), units 0..23 ============
        for (int mt = m_lo; mt < m_hi; mt++) {
            size_t base0 = ((size_t)(mt << 7) + wid * 16 + gid) * 256 + 4 * tig;
            size_t base8 = base0 + 8 * 256;

            uint32_t acc[12][2];
            #pragma unroll
            for (int i = 0; i < 12; i++) { acc[i][0] = 0u; acc[i][1] = 0u; }

            uint2 aC[4], aN[4];
            #pragma unroll
            for (int s = 0; s < 2; s++) {
                aC[2*s]   = ld2(hin + base0 + s * 16);
                aC[2*s+1] = ld2(hin + base8 + s * 16);
                if (use_comb) {
                    aC[2*s]   = add2(aC[2*s],   ld2(hin2 + base0 + s * 16));
                    aC[2*s+1] = add2(aC[2*s+1], ld2(hin2 + base8 + s * 16));
                }
            }

            for (int c = 0; c < 8; c++) {
                if (c < 7) {
                    int ko = (c + 1) * 32;
                    #pragma unroll
                    for (int s = 0; s < 2; s++) {
                        aN[2*s]   = ld2(hin + base0 + ko + s * 16);
                        aN[2*s+1] = ld2(hin + base8 + ko + s * 16);
                        if (use_comb) {
                            aN[2*s]   = add2(aN[2*s],   ld2(hin2 + base0 + ko + s * 16));
                            aN[2*s+1] = add2(aN[2*s+1], ld2(hin2 + base8 + ko + s * 16));
                        }
                    }
                }
                const uint32_t* Bb = smB + (size_t)c * 128 * AW;
                #pragma unroll
                for (int s = 0; s < 2; s++) {
                    uint32_t a0 = aC[2*s].x,   a2 = aC[2*s].y;
                    uint32_t a1 = aC[2*s+1].x, a3 = aC[2*s+1].y;
                    #pragma unroll
                    for (int g = 0; g < 4; g++)
                        #pragma unroll
                        for (int j = 0; j < 3; j++) {
                            const uint32_t* bp = Bb + (size_t)((g * 4 + j) * 8 + gid) * AW + s * 8 + tig;
                            mma_f16acc(acc[g * 3 + j], a0, a1, a2, a3, bp[0], bp[4]);
                        }
                }
                #pragma unroll
                for (int i = 0; i < 4; i++) aC[i] = aN[i];
            }

            // ---- epilogue (u 0..23) ----
            #pragma unroll
            for (int rr = 0; rr < 2; rr++) {
                int row = (mt << 7) + wid * 16 + gid + rr * 8;
                float xv[4];
                #pragma unroll
                for (int s = 0; s < 4; s++) xv[s] = x[(size_t)row * xstride + s];
                #pragma unroll
                for (int j = 0; j < 3; j++) {
                    int ub = 8 * j + 2 * tig;
                    size_t cb = (size_t)row * HID + nt * 32 + ub;
                    float2 cold = *(const float2*)(cin + cb);
                    if (use_comb) {
                        float2 c2 = *(const float2*)(cin2 + cb);
                        cold.x += c2.x; cold.y += c2.y;
                    }
                    float2 vi = __half22float2(H2(acc[    j][rr]));
                    float2 vf = __half22float2(H2(acc[3 + j][rr]));
                    float2 vg = __half22float2(H2(acc[6 + j][rr]));
                    float2 vo = __half22float2(H2(acc[9 + j][rr]));
                    float hv[2], cv[2];
                    #pragma unroll
                    for (int e = 0; e < 2; e++) {
                        int u = ub + e;
                        float g_i = (e == 0 ? vi.x : vi.y) + smBI[u];
                        float g_f = (e == 0 ? vf.x : vf.y) + smBI[32 + u];
                        float g_g = (e == 0 ? vg.x : vg.y) + smBI[64 + u];
                        float g_o = (e == 0 ? vo.x : vo.y) + smBI[96 + u];
                        #pragma unroll
                        for (int s = 0; s < 4; s++) {
                            g_i = fmaf(smWI[u * 4 + s],        xv[s], g_i);
                            g_f = fmaf(smWI[(32 + u) * 4 + s], xv[s], g_f);
                            g_g = fmaf(smWI[(64 + u) * 4 + s], xv[s], g_g);
                            g_o = fmaf(smWI[(96 + u) * 4 + s], xv[s], g_o);
                        }
                        float co = (e == 0) ? cold.x : cold.y;
                        float cn = fmaf(sig_fast(gclamp(g_f)), co,
                                        sig_fast(gclamp(g_i)) * tanh_fast(gclamp(g_g)));
                        float hn = sig_fast(gclamp(g_o)) * tanh_fast(gclamp(cn));
                        cv[e] = cn; hv[e] = hn;
                    }
                    *(float2*)(cout + cb) = make_float2(cv[0], cv[1]);
                    *(__half2*)(hout + cb) = __floats2half2_rn(hv[0], hv[1]);
                }
            }
        }
    } else {
        // ============ fma warps: lane = row within 32-row band, units 24..31 ============
        int fw = wid - 8;
        __half2 hz = __float2half2_rn(0.f);
        for (int mt = m_lo; mt < m_hi; mt++) {
            int row = (mt << 7) + fw * 32 + lane;
            const uint4* arow  = (const uint4*)(hin  + (size_t)row * 256);
            const uint4* arow2 = (const uint4*)(hin2 + (size_t)row * 256);

            __half2 acc[32];
            #pragma unroll
            for (int i = 0; i < 32; i++) acc[i] = hz;

            for (int c = 0; c < 8; c++) {
                uint4 Aq[4];
                #pragma unroll
                for (int i = 0; i < 4; i++) Aq[i] = arow[c * 4 + i];
                if (use_comb) {
                    #pragma unroll
                    for (int i = 0; i < 4; i++) {
                        uint4 b = arow2[c * 4 + i];
                        __half2 t;
                        t = __hadd2(H2(Aq[i].x), H2(b.x)); Aq[i].x = *(uint32_t*)&t;
                        t = __hadd2(H2(Aq[i].y), H2(b.y)); Aq[i].y = *(uint32_t*)&t;
                        t = __hadd2(H2(Aq[i].z), H2(b.z)); Aq[i].z = *(uint32_t*)&t;
                        t = __hadd2(H2(Aq[i].w), H2(b.w)); Aq[i].w = *(uint32_t*)&t;
                    }
                }
                #pragma unroll
                for (int s = 0; s < 2; s++) {
                    // phys k pairing: b0 words {0,4,8,12}+, b1 words {2,6,10,14}+ (perm)
                    __half2 p0 = H2(Aq[2*s].x), p1 = H2(Aq[2*s].y);
                    __half2 p2 = H2(Aq[2*s].z), p3 = H2(Aq[2*s].w);
                    __half2 p4 = H2(Aq[2*s+1].x), p5 = H2(Aq[2*s+1].y);
                    __half2 p6 = H2(Aq[2*s+1].z), p7 = H2(Aq[2*s+1].w);
                    const uint32_t* Bs = smB + (size_t)c * 128 * AW + s * 8;
                    #pragma unroll
                    for (int g = 0; g < 4; g++)
                        #pragma unroll
                        for (int uu = 0; uu < 8; uu++) {
                            const uint32_t* bp = Bs + (size_t)(g * 32 + 24 + uu) * AW;
                            uint4 b0 = *(const uint4*)(bp);      // phys {0,1},{4,5},{8,9},{12,13}
                            uint4 b1 = *(const uint4*)(bp + 4);  // phys {2,3},{6,7},{10,11},{14,15}
                            __half2 a = acc[g * 8 + uu];
                            a = __hfma2(H2(b0.x), p0, a);
                            a = __hfma2(H2(b1.x), p1, a);
                            a = __hfma2(H2(b0.y), p2, a);
                            a = __hfma2(H2(b1.y), p3, a);
                            a = __hfma2(H2(b0.z), p4, a);
                            a = __hfma2(H2(b1.z), p5, a);
                            a = __hfma2(H2(b0.w), p6, a);
                            a = __hfma2(H2(b1.w), p7, a);
                            acc[g * 8 + uu] = a;
                        }
                }
            }

            // ---- epilogue (u 24..31) ----
            float xv[4];
            #pragma unroll
            for (int s = 0; s < 4; s++) xv[s] = x[(size_t)row * xstride + s];
            size_t cbase = (size_t)row * HID + nt * 32 + 24;
            #pragma unroll
            for (int q = 0; q < 4; q++) {
                float2 cold = *(const float2*)(cin + cbase + 2 * q);
                if (use_comb) {
                    float2 c2 = *(const float2*)(cin2 + cbase + 2 * q);
                    cold.x += c2.x; cold.y += c2.y;
                }
                float hv[2], cv[2];
                #pragma unroll
                for (int e = 0; e < 2; e++) {
                    int uu = 2 * q + e;
                    int u = 24 + uu;
                    float2 ti = __half22float2(acc[     uu]);
                    float2 tf = __half22float2(acc[ 8 + uu]);
                    float2 tg = __half22float2(acc[16 + uu]);
                    float2 to = __half22float2(acc[24 + uu]);
                    float g_i = ti.x + ti.y + smBI[u];
                    float g_f = tf.x + tf.y + smBI[32 + u];
                    float g_g = tg.x + tg.y + smBI[64 + u];
                    float g_o = to.x + to.y + smBI[96 + u];
                    #pragma unroll
                    for (int s = 0; s < 4; s++) {
                        g_i = fmaf(smWI[u * 4 + s],        xv[s], g_i);
                        g_f = fmaf(smWI[(32 + u) * 4 + s], xv[s], g_f);
                        g_g = fmaf(smWI[(64 + u) * 4 + s], xv[s], g_g);
                        g_o = fmaf(smWI[(96 + u) * 4 + s], xv[s], g_o);
                    }
                    float co = (e == 0) ? cold.x : cold.y;
                    float cn = fmaf(sig_fast(gclamp(g_f)), co,
                                    sig_fast(gclamp(g_i)) * tanh_fast(gclamp(g_g)));
                    float hn = sig_fast(gclamp(g_o)) * tanh_fast(gclamp(cn));
                    cv[e] = cn; hv[e] = hn;
                }
                *(float2*)(cout + cbase + 2 * q) = make_float2(cv[0], cv[1]);
                *(__half2*)(hout + cbase + 2 * q) = __floats2half2_rn(hv[0], hv[1]);
            }
        }
    }
}

// ---------------- decoder heads ----------------
__global__ void heads_kernel(int t, int parity,
    const float* __restrict__ fsw, const float* __restrict__ fsb,
    const float* __restrict__ fcw, const float* __restrict__ fcb,
    const float* __restrict__ ew,  const float* __restrict__ eb,
    float* __restrict__ out)
{
    int gtid = blockIdx.x * blockDim.x + threadIdx.x;
    int row  = gtid >> 5;
    int lane = gtid & 31;
    if (row >= NB) return;
    const __half* hs = d_hbuf[2][parity] + (size_t)row * HID;
    const __half* hc = d_hbuf[3][parity] + (size_t)row * HID;
    float vs[8], vc[8];
    #pragma unroll
    for (int i = 0; i < 8; i++) {
        vs[i] = __half2float(hs[lane + 32 * i]);
        vc[i] = __half2float(hc[lane + 32 * i]);
    }

    float r[10];
    #pragma unroll
    for (int o = 0; o < 4; o++) {
        float p = 0.f;
        #pragma unroll
        for (int i = 0; i < 8; i++) p = fmaf(fsw[o * 256 + lane + 32 * i], vs[i], p);
        r[o] = p;
    }
    #pragma unroll
    for (int o = 0; o < 2; o++) {
        float p = 0.f;
        #pragma unroll
        for (int i = 0; i < 8; i++) p = fmaf(fcw[o * 256 + lane + 32 * i], vc[i], p);
        r[4 + o] = p;
    }
    #pragma unroll
    for (int o = 0; o < 4; o++) {
        float p = 0.f;
        #pragma unroll
        for (int i = 0; i < 8; i++) p = fmaf(ew[o * 256 + lane + 32 * i], vc[i], p);
        r[6 + o] = p;
    }
    #pragma unroll
    for (int off = 16; off > 0; off >>= 1)
        #pragma unroll
        for (int o = 0; o < 10; o++) r[o] += __shfl_xor_sync(0xffffffffu, r[o], off);

    if (lane == 0) {
        #pragma unroll
        for (int s = 0; s < 4; s++) {
            float v = r[s] + fsb[s];
            v = fminf(fmaxf(v, -100.f), 100.f);
            out[(size_t)row * 64 + t * 4 + s] = v;
            d_xs[row * 4 + s] = v;
        }
        float l0 = fmaxf(r[4] + fcb[0], 0.f);
        float l1 = fmaxf(r[5] + fcb[1], 0.f);
        float m  = fmaxf(l0, l1);
        float e0 = expf(l0 - m), e1 = expf(l1 - m);
        float inv = 1.f / (e0 + e1);
        size_t cb = (size_t)NB * 64;
        out[cb + (size_t)row * 32 + t * 2 + 0] = e0 * inv;
        out[cb + (size_t)row * 32 + t * 2 + 1] = e1 * inv;
        #pragma unroll
        for (int s = 0; s < 4; s++) d_xc[row * 4 + s] = fmaxf(r[6 + s] + eb[s], 0.f);
    }
}

// ---------------- host ----------------
extern "C" void kernel_launch(void* const* d_in, const int* in_sizes, int n_in,
                              void* d_out, int out_size)
{
    (void)in_sizes; (void)n_in; (void)out_size;
    const float* speed = (const float*)d_in[0];
    const float* pos   = (const float*)d_in[1];

    cudaFuncSetAttribute(cell_mma_kernel, cudaFuncAttributeMaxDynamicSharedMemorySize, SM_TOTAL);

    for (int cell = 0; cell < 4; cell++) {
        int base = 2 + 4 * cell;
        prep_kernel<<<1024, 256>>>(cell,
            (const float*)d_in[base + 1],
            (const float*)d_in[base + 0],
            (const float*)d_in[base + 2],
            (const float*)d_in[base + 3]);
    }

    dim3 tgrid(8, 2, MSPLIT);

    // ---- encoders (cells 0,1) ----
    cell_first_kernel<<<dim3(8, 128, 2), 256>>>(speed, pos, 64);
    for (int t = 1; t < 16; t++)
        cell_mma_kernel<<<tgrid, 384, SM_TOTAL>>>(0, speed + 4 * t, pos + 4 * t, 64, t & 1, 0, 0);

    // ---- decoders (cells 2,3); t=0 fuses encoder-state combine ----
    const float* fsw = (const float*)d_in[18];
    const float* fsb = (const float*)d_in[19];
    const float* fcw = (const float*)d_in[20];
    const float* fcb = (const float*)d_in[21];
    const float* ew  = (const float*)d_in[22];
    const float* eb  = (const float*)d_in[23];
    float* out = (float*)d_out;

    for (int t = 0; t < TOUT; t++) {
        if (t == 0)
            cell_mma_kernel<<<tgrid, 384, SM_TOTAL>>>(2, speed + 60, pos + 60, 64, 0, 1, 0);
        else
            cell_mma_kernel<<<tgrid, 384, SM_TOTAL>>>(2, nullptr, nullptr, 4, t & 1, 0, 1);
        heads_kernel<<<2048, 256>>>(t, (t & 1) ^ 1, fsw, fsb, fcw, fcb, ew, eb, out);
    }
}

// round 9
// speedup vs baseline: 1.4204x; 1.4204x over previous
#include <cuda_runtime.h>
#include <cuda_fp16.h>
#include <math.h>
#include <stdint.h>

#define NB   16384
#define HID  256
#define TOUT 16
#define MSPLIT 9

// ---------------- persistent device scratch ----------------
__device__ float  d_W4h[4][1024 * 256];   // permuted recurrent weights [col'][k] (fp32)
__device__ float  d_W4i[4][1024 * 4];
__device__ float  d_b4 [4][1024];
__device__ __half d_hbuf[4][2][NB * HID]; // hidden state, fp16
__device__ float  d_cbuf[4][NB * HID];    // cell state, fp32
__device__ __half d_h0c[NB * HID];
__device__ float  d_c0c[NB * HID];
__device__ float  d_xs[NB * 4];
__device__ float  d_xc[NB * 4];

__device__ __forceinline__ float sigf(float x) { return 1.0f / (1.0f + expf(-x)); }
__device__ __forceinline__ float sig_fast(float x) {
    float e = __expf(-x);
    return __fdividef(1.0f, 1.0f + e);
}
__device__ __forceinline__ float tanh_fast(float x) {
    float e = __expf(-2.0f * x);
    return (1.0f - e) * __fdividef(1.0f, 1.0f + e);
}
__device__ __forceinline__ float gclamp(float x) { return fminf(fmaxf(x, -30.0f), 30.0f); }

__device__ __forceinline__ void mma_f16acc(uint32_t* d,
    uint32_t a0, uint32_t a1, uint32_t a2, uint32_t a3, uint32_t b0, uint32_t b1) {
    asm volatile("mma.sync.aligned.m16n8k16.row.col.f16.f16.f16.f16 "
        "{%0,%1}, {%2,%3,%4,%5}, {%6,%7}, {%0,%1};"
        : "+r"(d[0]), "+r"(d[1])
        : "r"(a0), "r"(a1), "r"(a2), "r"(a3), "r"(b0), "r"(b1));
}

__device__ __forceinline__ __half2 H2(uint32_t u) { return *(__half2*)&u; }

// ---------------- SMEM layout ----------------
// word = uint32 holding half2 (2 halfs along k). Row stride 20 words (16 data + 4 pad)
#define AW 20
#define SM_WI   0                        // 128*4 floats = 2048 B
#define SM_BI   2048                     // 512 B
#define SM_A    2560                     // 2*128*20*4 = 20480 B
#define SM_B    23040                    // 8*128*20*4 = 81920 B
#define SM_TOTAL 104960

// ---------------- weight permutation ----------------
__global__ void prep_kernel(int cell,
                            const float* __restrict__ Whh,
                            const float* __restrict__ Wih,
                            const float* __restrict__ bih,
                            const float* __restrict__ bhh) {
    int colp = blockIdx.x;
    int k    = threadIdx.x;
    int g    = (colp & 127) >> 5;
    int u    = ((colp >> 7) << 5) + (colp & 31);
    int orig = g * 256 + u;
    d_W4h[cell][colp * 256 + k] = Whh[orig * 256 + k];
    if (k < 4) d_W4i[cell][colp * 4 + k] = Wih[orig * 4 + k];
    if (k == 0) d_b4[cell][colp] = bih[orig] + bhh[orig];
}

// ---------------- first step (h=c=0) ----------------
__global__ __launch_bounds__(256, 2) void cell_first_kernel(
    const float* __restrict__ x0, const float* __restrict__ x1, int xstride)
{
    int cell = blockIdx.z;
    const float* x = blockIdx.z == 0 ? x0 : x1;
    __half* hout = d_hbuf[cell][1];
    float*  cout = d_cbuf[cell];
    int row0 = blockIdx.y << 7;
    int col0 = blockIdx.x << 7;
    int tx = threadIdx.x & 15;
    int ty = threadIdx.x >> 4;

    float xv[8][4];
    #pragma unroll
    for (int rr = 0; rr < 8; rr++) {
        int row = row0 + (ty << 3) + rr;
        #pragma unroll
        for (int s = 0; s < 4; s++) xv[rr][s] = x[(size_t)row * xstride + s];
    }
    const float* Wi = d_W4i[cell];
    const float* bb = d_b4[cell];
    int ubase = blockIdx.x << 5;

    #pragma unroll
    for (int hh = 0; hh < 2; hh++) {
        int u = ubase + tx + (hh << 4);
        float wi[4][4], bg[4];
        #pragma unroll
        for (int g = 0; g < 4; g++) {
            int colp = col0 + (g << 5) + tx + (hh << 4);
            bg[g] = bb[colp];
            #pragma unroll
            for (int s = 0; s < 4; s++) wi[g][s] = Wi[colp * 4 + s];
        }
        #pragma unroll
        for (int rr = 0; rr < 8; rr++) {
            int row = row0 + (ty << 3) + rr;
            float gt[4];
            #pragma unroll
            for (int g = 0; g < 4; g++) {
                float v = bg[g];
                #pragma unroll
                for (int s = 0; s < 4; s++) v = fmaf(wi[g][s], xv[rr][s], v);
                gt[g] = v;
            }
            float ig = sigf(gt[0]);
            float gg = tanhf(gt[2]);
            float og = sigf(gt[3]);
            float cn = ig * gg;
            float hn = og * tanhf(cn);
            cout[(size_t)row * HID + u] = cn;
            hout[(size_t)row * HID + u] = __float2half(hn);
        }
    }
}

// ---------------- hybrid tensor+fma LSTM step (R6 skeleton) ----------------
// block 384 = 8 tensor warps (u 0-23) + 4 fma warps (u 24-31).
// A staged in double-buffered smA by threads 0-255 (coalesced), 1 sync/chunk.
__global__ __launch_bounds__(384, 1) void cell_mma_kernel(
    int cell_base, const float* __restrict__ x0, const float* __restrict__ x1,
    int xstride, int rd, int use_comb, int use_fb)
{
    extern __shared__ char smem[];
    uint32_t* smA = (uint32_t*)(smem + SM_A);   // [2][128][AW]
    uint32_t* smB = (uint32_t*)(smem + SM_B);   // [8][128][AW]
    float* smWI = (float*)(smem + SM_WI);
    float* smBI = (float*)(smem + SM_BI);

    int tid = threadIdx.x;
    int wid = tid >> 5, lane = tid & 31;
    int gid = lane >> 2, tig = lane & 3;
    int cell = cell_base + blockIdx.y;
    const float* x = use_fb ? (blockIdx.y == 0 ? d_xs : d_xc)
                            : (blockIdx.y == 0 ? x0 : x1);
    const __half* hin = use_comb ? d_h0c : d_hbuf[cell][rd];
    const float*  cin = use_comb ? d_c0c : d_cbuf[cell];
    __half* hout = d_hbuf[cell][rd ^ 1];
    float*  cout = d_cbuf[cell];
    const float* Wh = d_W4h[cell];
    int nt = blockIdx.x;
    int col0 = nt << 7;
    int m_lo = (blockIdx.z * 128) / MSPLIT;
    int m_hi = ((blockIdx.z + 1) * 128) / MSPLIT;

    int r = tid >> 1, half = tid & 1;

    // ---- load resident weight tile (fp32 -> half2), Wi, bias (threads 0-255) ----
    if (tid < 256) {
        const float* wrow = Wh + (size_t)(col0 + r) * 256 + half * 16;
        #pragma unroll
        for (int c = 0; c < 8; c++) {
            const float* src = wrow + c * 32;
            uint32_t w[8];
            #pragma unroll
            for (int j = 0; j < 8; j++) {
                __half2 h2 = __floats2half2_rn(src[2 * j], src[2 * j + 1]);
                w[j] = *(uint32_t*)&h2;
            }
            uint32_t* dst = smB + ((size_t)c * 128 + r) * AW + half * 8;
            *(uint4*)(dst)     = make_uint4(w[0], w[1], w[2], w[3]);
            *(uint4*)(dst + 4) = make_uint4(w[4], w[5], w[6], w[7]);
        }
        if (tid < 128)
            *(float4*)(smWI + tid * 4) = *(const float4*)(d_W4i[cell] + (size_t)(col0 + tid) * 4);
        if (tid < 32)
            *(float4*)(smBI + tid * 4) = *(const float4*)(d_b4[cell] + col0 + tid * 4);
    }
    __syncthreads();

    // prologue: preload chunk 0 of first mtile (staging threads only)
    uint4 va0, va1;
    if (tid < 256) {
        const uint4* arow = (const uint4*)(hin + (size_t)((m_lo << 7) + r) * 256 + half * 16);
        va0 = arow[0]; va1 = arow[1];
    }

    for (int mt = m_lo; mt < m_hi; mt++) {
        int row0 = mt << 7;
        const uint4* arow = (const uint4*)(hin + (size_t)(row0 + r) * 256 + half * 16);

        if (wid < 8) {
            // ======== tensor warps: also do staging; compute u 0..23 ========
            uint32_t acc[12][2];
            #pragma unroll
            for (int i = 0; i < 12; i++) { acc[i][0] = 0u; acc[i][1] = 0u; }

            for (int c = 0; c < 8; c++) {
                uint32_t* dst = smA + (size_t)((c & 1) * 128 + r) * AW + half * 8;
                *(uint4*)(dst)     = va0;
                *(uint4*)(dst + 4) = va1;
                __syncthreads();
                if (c < 7) {
                    va0 = arow[(c + 1) * 4 + 0];
                    va1 = arow[(c + 1) * 4 + 1];
                } else if (mt + 1 < m_hi) {
                    const uint4* arow2 = (const uint4*)(hin + (size_t)(row0 + 128 + r) * 256 + half * 16);
                    va0 = arow2[0]; va1 = arow2[1];
                }
                const uint32_t* Ab = smA + (size_t)((c & 1) * 128 + wid * 16) * AW;
                const uint32_t* Bb = smB + (size_t)c * 128 * AW;
                #pragma unroll
                for (int s = 0; s < 2; s++) {
                    int kk = s * 8;
                    uint32_t a0 = Ab[(size_t)gid * AW + kk + tig];
                    uint32_t a1 = Ab[(size_t)(gid + 8) * AW + kk + tig];
                    uint32_t a2 = Ab[(size_t)gid * AW + kk + tig + 4];
                    uint32_t a3 = Ab[(size_t)(gid + 8) * AW + kk + tig + 4];
                    #pragma unroll
                    for (int g = 0; g < 4; g++)
                        #pragma unroll
                        for (int j = 0; j < 3; j++) {
                            int n8 = g * 4 + j;
                            uint32_t b0 = Bb[(size_t)(n8 * 8 + gid) * AW + kk + tig];
                            uint32_t b1 = Bb[(size_t)(n8 * 8 + gid) * AW + kk + tig + 4];
                            mma_f16acc(acc[g * 3 + j], a0, a1, a2, a3, b0, b1);
                        }
                }
            }

            // ---- epilogue u 0..23 ----
            #pragma unroll
            for (int rr = 0; rr < 2; rr++) {
                int row = row0 + wid * 16 + gid + rr * 8;
                float xv[4];
                #pragma unroll
                for (int s = 0; s < 4; s++) xv[s] = x[(size_t)row * xstride + s];
                #pragma unroll
                for (int j = 0; j < 3; j++) {
                    int ub = 8 * j + 2 * tig;
                    size_t cb = (size_t)row * HID + nt * 32 + ub;
                    float2 cold = *(const float2*)(cin + cb);
                    float2 vi = __half22float2(H2(acc[    j][rr]));
                    float2 vf = __half22float2(H2(acc[3 + j][rr]));
                    float2 vg = __half22float2(H2(acc[6 + j][rr]));
                    float2 vo = __half22float2(H2(acc[9 + j][rr]));
                    float hv[2], cv[2];
                    #pragma unroll
                    for (int e = 0; e < 2; e++) {
                        int u = ub + e;
                        float g_i = (e == 0 ? vi.x : vi.y) + smBI[u];
                        float g_f = (e == 0 ? vf.x : vf.y) + smBI[32 + u];
                        float g_g = (e == 0 ? vg.x : vg.y) + smBI[64 + u];
                        float g_o = (e == 0 ? vo.x : vo.y) + smBI[96 + u];
                        #pragma unroll
                        for (int s = 0; s < 4; s++) {
                            g_i = fmaf(smWI[u * 4 + s],        xv[s], g_i);
                            g_f = fmaf(smWI[(32 + u) * 4 + s], xv[s], g_f);
                            g_g = fmaf(smWI[(64 + u) * 4 + s], xv[s], g_g);
                            g_o = fmaf(smWI[(96 + u) * 4 + s], xv[s], g_o);
                        }
                        float co = (e == 0) ? cold.x : cold.y;
                        float cn = fmaf(sig_fast(gclamp(g_f)), co,
                                        sig_fast(gclamp(g_i)) * tanh_fast(gclamp(g_g)));
                        float hn = sig_fast(gclamp(g_o)) * tanh_fast(gclamp(cn));
                        cv[e] = cn; hv[e] = hn;
                    }
                    *(float2*)(cout + cb) = make_float2(cv[0], cv[1]);
                    *(__half2*)(hout + cb) = __floats2half2_rn(hv[0], hv[1]);
                }
            }
        } else {
            // ======== fma warps: lane = row in band, compute u 24..31 from smA ========
            int fw = wid - 8;
            int row_local = fw * 32 + lane;
            __half2 hz = __float2half2_rn(0.f);
            __half2 acc[32];
            #pragma unroll
            for (int i = 0; i < 32; i++) acc[i] = hz;

            for (int c = 0; c < 8; c++) {
                __syncthreads();   // pairs with staging sync
                const uint32_t* Ar = smA + (size_t)((c & 1) * 128 + row_local) * AW;
                uint4 q0 = *(const uint4*)(Ar);
                uint4 q1 = *(const uint4*)(Ar + 4);
                uint4 q2 = *(const uint4*)(Ar + 8);
                uint4 q3 = *(const uint4*)(Ar + 12);
                __half2 p[16];
                p[0]=H2(q0.x); p[1]=H2(q0.y); p[2]=H2(q0.z); p[3]=H2(q0.w);
                p[4]=H2(q1.x); p[5]=H2(q1.y); p[6]=H2(q1.z); p[7]=H2(q1.w);
                p[8]=H2(q2.x); p[9]=H2(q2.y); p[10]=H2(q2.z); p[11]=H2(q2.w);
                p[12]=H2(q3.x); p[13]=H2(q3.y); p[14]=H2(q3.z); p[15]=H2(q3.w);
                const uint32_t* Bc = smB + (size_t)c * 128 * AW;
                #pragma unroll
                for (int g = 0; g < 4; g++)
                    #pragma unroll
                    for (int uu = 0; uu < 8; uu++) {
                        const uint32_t* bp = Bc + (size_t)(g * 32 + 24 + uu) * AW;
                        uint4 b0 = *(const uint4*)(bp);
                        uint4 b1 = *(const uint4*)(bp + 4);
                        uint4 b2 = *(const uint4*)(bp + 8);
                        uint4 b3 = *(const uint4*)(bp + 12);
                        __half2 a = acc[g * 8 + uu];
                        a = __hfma2(H2(b0.x), p[0],  a);
                        a = __hfma2(H2(b0.y), p[1],  a);
                        a = __hfma2(H2(b0.z), p[2],  a);
                        a = __hfma2(H2(b0.w), p[3],  a);
                        a = __hfma2(H2(b1.x), p[4],  a);
                        a = __hfma2(H2(b1.y), p[5],  a);
                        a = __hfma2(H2(b1.z), p[6],  a);
                        a = __hfma2(H2(b1.w), p[7],  a);
                        a = __hfma2(H2(b2.x), p[8],  a);
                        a = __hfma2(H2(b2.y), p[9],  a);
                        a = __hfma2(H2(b2.z), p[10], a);
                        a = __hfma2(H2(b2.w), p[11], a);
                        a = __hfma2(H2(b3.x), p[12], a);
                        a = __hfma2(H2(b3.y), p[13], a);
                        a = __hfma2(H2(b3.z), p[14], a);
                        a = __hfma2(H2(b3.w), p[15], a);
                        acc[g * 8 + uu] = a;
                    }
            }

            // ---- epilogue u 24..31 ----
            int row = row0 + row_local;
            float xv[4];
            #pragma unroll
            for (int s = 0; s < 4; s++) xv[s] = x[(size_t)row * xstride + s];
            size_t cbase = (size_t)row * HID + nt * 32 + 24;
            #pragma unroll
            for (int q = 0; q < 4; q++) {
                float2 cold = *(const float2*)(cin + cbase + 2 * q);
                float hv[2], cv[2];
                #pragma unroll
                for (int e = 0; e < 2; e++) {
                    int uu = 2 * q + e;
                    int u = 24 + uu;
                    float2 ti = __half22float2(acc[     uu]);
                    float2 tf = __half22float2(acc[ 8 + uu]);
                    float2 tg = __half22float2(acc[16 + uu]);
                    float2 to = __half22float2(acc[24 + uu]);
                    float g_i = ti.x + ti.y + smBI[u];
                    float g_f = tf.x + tf.y + smBI[32 + u];
                    float g_g = tg.x + tg.y + smBI[64 + u];
                    float g_o = to.x + to.y + smBI[96 + u];
                    #pragma unroll
                    for (int s = 0; s < 4; s++) {
                        g_i = fmaf(smWI[u * 4 + s],        xv[s], g_i);
                        g_f = fmaf(smWI[(32 + u) * 4 + s], xv[s], g_f);
                        g_g = fmaf(smWI[(64 + u) * 4 + s], xv[s], g_g);
                        g_o = fmaf(smWI[(96 + u) * 4 + s], xv[s], g_o);
                    }
                    float co = (e == 0) ? cold.x : cold.y;
                    float cn = fmaf(sig_fast(gclamp(g_f)), co,
                                    sig_fast(gclamp(g_i)) * tanh_fast(gclamp(g_g)));
                    float hn = sig_fast(gclamp(g_o)) * tanh_fast(gclamp(cn));
                    cv[e] = cn; hv[e] = hn;
                }
                *(float2*)(cout + cbase + 2 * q) = make_float2(cv[0], cv[1]);
                *(__half2*)(hout + cbase + 2 * q) = __floats2half2_rn(hv[0], hv[1]);
            }
        }
    }
}

// ---------------- combine encoder finals ----------------
__global__ void combine_kernel() {
    size_t i = (size_t)blockIdx.x * blockDim.x + threadIdx.x;
    float4 c0 = ((const float4*)d_cbuf[0])[i];
    float4 c1 = ((const float4*)d_cbuf[1])[i];
    ((float4*)d_c0c)[i] = make_float4(c0.x + c1.x, c0.y + c1.y, c0.z + c1.z, c0.w + c1.w);
    const __half2* ha = (const __half2*)d_hbuf[0][0];
    const __half2* hb = (const __half2*)d_hbuf[1][0];
    __half2* ho = (__half2*)d_h0c;
    #pragma unroll
    for (int j = 0; j < 2; j++) {
        float2 a = __half22float2(ha[2 * i + j]);
        float2 b = __half22float2(hb[2 * i + j]);
        ho[2 * i + j] = __floats2half2_rn(a.x + b.x, a.y + b.y);
    }
}

// ---------------- decoder heads ----------------
__global__ void heads_kernel(int t, int parity,
    const float* __restrict__ fsw, const float* __restrict__ fsb,
    const float* __restrict__ fcw, const float* __restrict__ fcb,
    const float* __restrict__ ew,  const float* __restrict__ eb,
    float* __restrict__ out)
{
    int gtid = blockIdx.x * blockDim.x + threadIdx.x;
    int row  = gtid >> 5;
    int lane = gtid & 31;
    if (row >= NB) return;
    const __half* hs = d_hbuf[2][parity] + (size_t)row * HID;
    const __half* hc = d_hbuf[3][parity] + (size_t)row * HID;
    float vs[8], vc[8];
    #pragma unroll
    for (int i = 0; i < 8; i++) {
        vs[i] = __half2float(hs[lane + 32 * i]);
        vc[i] = __half2float(hc[lane + 32 * i]);
    }

    float r[10];
    #pragma unroll
    for (int o = 0; o < 4; o++) {
        float p = 0.f;
        #pragma unroll
        for (int i = 0; i < 8; i++) p = fmaf(fsw[o * 256 + lane + 32 * i], vs[i], p);
        r[o] = p;
    }
    #pragma unroll
    for (int o = 0; o < 2; o++) {
        float p = 0.f;
        #pragma unroll
        for (int i = 0; i < 8; i++) p = fmaf(fcw[o * 256 + lane + 32 * i], vc[i], p);
        r[4 + o] = p;
    }
    #pragma unroll
    for (int o = 0; o < 4; o++) {
        float p = 0.f;
        #pragma unroll
        for (int i = 0; i < 8; i++) p = fmaf(ew[o * 256 + lane + 32 * i], vc[i], p);
        r[6 + o] = p;
    }
    #pragma unroll
    for (int off = 16; off > 0; off >>= 1)
        #pragma unroll
        for (int o = 0; o < 10; o++) r[o] += __shfl_xor_sync(0xffffffffu, r[o], off);

    if (lane == 0) {
        #pragma unroll
        for (int s = 0; s < 4; s++) {
            float v = r[s] + fsb[s];
            v = fminf(fmaxf(v, -100.f), 100.f);
            out[(size_t)row * 64 + t * 4 + s] = v;
            d_xs[row * 4 + s] = v;
        }
        float l0 = fmaxf(r[4] + fcb[0], 0.f);
        float l1 = fmaxf(r[5] + fcb[1], 0.f);
        float m  = fmaxf(l0, l1);
        float e0 = expf(l0 - m), e1 = expf(l1 - m);
        float inv = 1.f / (e0 + e1);
        size_t cb = (size_t)NB * 64;
        out[cb + (size_t)row * 32 + t * 2 + 0] = e0 * inv;
        out[cb + (size_t)row * 32 + t * 2 + 1] = e1 * inv;
        #pragma unroll
        for (int s = 0; s < 4; s++) d_xc[row * 4 + s] = fmaxf(r[6 + s] + eb[s], 0.f);
    }
}

// ---------------- host ----------------
extern "C" void kernel_launch(void* const* d_in, const int* in_sizes, int n_in,
                              void* d_out, int out_size)
{
    (void)in_sizes; (void)n_in; (void)out_size;
    const float* speed = (const float*)d_in[0];
    const float* pos   = (const float*)d_in[1];

    cudaFuncSetAttribute(cell_mma_kernel, cudaFuncAttributeMaxDynamicSharedMemorySize, SM_TOTAL);

    for (int cell = 0; cell < 4; cell++) {
        int base = 2 + 4 * cell;
        prep_kernel<<<1024, 256>>>(cell,
            (const float*)d_in[base + 1],
            (const float*)d_in[base + 0],
            (const float*)d_in[base + 2],
            (const float*)d_in[base + 3]);
    }

    dim3 tgrid(8, 2, MSPLIT);

    // ---- encoders ----
    cell_first_kernel<<<dim3(8, 128, 2), 256>>>(speed, pos, 64);
    for (int t = 1; t < 16; t++)
        cell_mma_kernel<<<tgrid, 384, SM_TOTAL>>>(0, speed + 4 * t, pos + 4 * t, 64, t & 1, 0, 0);

    combine_kernel<<<4096, 256>>>();

    // ---- decoders ----
    const float* fsw = (const float*)d_in[18];
    const float* fsb = (const float*)d_in[19];
    const float* fcw = (const float*)d_in[20];
    const float* fcb = (const float*)d_in[21];
    const float* ew  = (const float*)d_in[22];
    const float* eb  = (const float*)d_in[23];
    float* out = (float*)d_out;

    for (int t = 0; t < TOUT; t++) {
        if (t == 0)
            cell_mma_kernel<<<tgrid, 384, SM_TOTAL>>>(2, speed + 60, pos + 60, 64, 0, 1, 0);
        else
            cell_mma_kernel<<<tgrid, 384, SM_TOTAL>>>(2, nullptr, nullptr, 4, t & 1, 0, 1);
        heads_kernel<<<2048, 256>>>(t, (t & 1) ^ 1, fsw, fsb, fcw, fcb, ew, eb, out);
    }
}

// round 11
// speedup vs baseline: 1.6472x; 1.1597x over previous
#include <cuda_runtime.h>
#include <cuda_fp16.h>
#include <math.h>
#include <stdint.h>

#define NB   16384
#define HID  256
#define TOUT 16
#define MSPLIT 9

// ---------------- persistent device scratch ----------------
__device__ float  d_W4h[4][1024 * 256];   // permuted recurrent weights [col'][k] (fp32)
__device__ float  d_W4i[4][1024 * 4];
__device__ float  d_b4 [4][1024];
__device__ __half d_hbuf[4][2][NB * HID]; // hidden state, fp16
__device__ float  d_cbuf[4][NB * HID];    // cell state, fp32
__device__ __half d_h0c[NB * HID];
__device__ float  d_c0c[NB * HID];
__device__ float  d_xs[NB * 4];
__device__ float  d_xc[NB * 4];

__device__ __forceinline__ float sigf(float x) { return 1.0f / (1.0f + expf(-x)); }
__device__ __forceinline__ float sig_fast(float x) {
    float e = __expf(-x);
    return __fdividef(1.0f, 1.0f + e);
}
__device__ __forceinline__ float tanh_fast(float x) {
    float e = __expf(-2.0f * x);
    return (1.0f - e) * __fdividef(1.0f, 1.0f + e);
}
__device__ __forceinline__ float gclamp(float x) { return fminf(fmaxf(x, -30.0f), 30.0f); }

__device__ __forceinline__ void mma_f16acc(uint32_t* d,
    uint32_t a0, uint32_t a1, uint32_t a2, uint32_t a3, uint32_t b0, uint32_t b1) {
    asm volatile("mma.sync.aligned.m16n8k16.row.col.f16.f16.f16.f16 "
        "{%0,%1}, {%2,%3,%4,%5}, {%6,%7}, {%0,%1};"
        : "+r"(d[0]), "+r"(d[1])
        : "r"(a0), "r"(a1), "r"(a2), "r"(a3), "r"(b0), "r"(b1));
}

__device__ __forceinline__ __half2 H2(uint32_t u) { return *(__half2*)&u; }

// ---------------- SMEM layout ----------------
#define AW 20
#define SM_WI   0                        // 128*4 floats = 2048 B
#define SM_BI   2048                     // 512 B
#define SM_A    2560                     // 2*128*20*4 = 20480 B
#define SM_B    23040                    // 8*128*20*4 = 81920 B
#define SM_TOTAL 104960

// ---------------- weight permutation ----------------
__global__ void prep_kernel(int cell,
                            const float* __restrict__ Whh,
                            const float* __restrict__ Wih,
                            const float* __restrict__ bih,
                            const float* __restrict__ bhh) {
    int colp = blockIdx.x;
    int k    = threadIdx.x;
    int g    = (colp & 127) >> 5;
    int u    = ((colp >> 7) << 5) + (colp & 31);
    int orig = g * 256 + u;
    d_W4h[cell][colp * 256 + k] = Whh[orig * 256 + k];
    if (k < 4) d_W4i[cell][colp * 4 + k] = Wih[orig * 4 + k];
    if (k == 0) d_b4[cell][colp] = bih[orig] + bhh[orig];
}

// ---------------- first step (h=c=0) ----------------
__global__ __launch_bounds__(256, 2) void cell_first_kernel(
    const float* __restrict__ x0, const float* __restrict__ x1, int xstride)
{
    int cell = blockIdx.z;
    const float* x = blockIdx.z == 0 ? x0 : x1;
    __half* hout = d_hbuf[cell][1];
    float*  cout = d_cbuf[cell];
    int row0 = blockIdx.y << 7;
    int col0 = blockIdx.x << 7;
    int tx = threadIdx.x & 15;
    int ty = threadIdx.x >> 4;

    float xv[8][4];
    #pragma unroll
    for (int rr = 0; rr < 8; rr++) {
        int row = row0 + (ty << 3) + rr;
        #pragma unroll
        for (int s = 0; s < 4; s++) xv[rr][s] = x[(size_t)row * xstride + s];
    }
    const float* Wi = d_W4i[cell];
    const float* bb = d_b4[cell];
    int ubase = blockIdx.x << 5;

    #pragma unroll
    for (int hh = 0; hh < 2; hh++) {
        int u = ubase + tx + (hh << 4);
        float wi[4][4], bg[4];
        #pragma unroll
        for (int g = 0; g < 4; g++) {
            int colp = col0 + (g << 5) + tx + (hh << 4);
            bg[g] = bb[colp];
            #pragma unroll
            for (int s = 0; s < 4; s++) wi[g][s] = Wi[colp * 4 + s];
        }
        #pragma unroll
        for (int rr = 0; rr < 8; rr++) {
            int row = row0 + (ty << 3) + rr;
            float gt[4];
            #pragma unroll
            for (int g = 0; g < 4; g++) {
                float v = bg[g];
                #pragma unroll
                for (int s = 0; s < 4; s++) v = fmaf(wi[g][s], xv[rr][s], v);
                gt[g] = v;
            }
            float ig = sigf(gt[0]);
            float gg = tanhf(gt[2]);
            float og = sigf(gt[3]);
            float cn = ig * gg;
            float hn = og * tanhf(cn);
            cout[(size_t)row * HID + u] = cn;
            hout[(size_t)row * HID + u] = __float2half(hn);
        }
    }
}

// ---------------- fp16 mma.sync LSTM step, software-pipelined epilogue ----------------
// grid (8 N-tiles, 2 cells, MSPLIT M-groups), 256 threads = 8 warps.
// Two acc sets: epilogue of mtile t-1 interleaved into chunks 0-3 of mtile t.
__global__ __launch_bounds__(256, 1) void cell_mma_kernel(
    int cell_base, const float* __restrict__ x0, const float* __restrict__ x1,
    int xstride, int rd, int use_comb, int use_fb)
{
    extern __shared__ char smem[];
    uint32_t* smA = (uint32_t*)(smem + SM_A);   // [2][128][AW]
    uint32_t* smB = (uint32_t*)(smem + SM_B);   // [8][128][AW]
    float* smWI = (float*)(smem + SM_WI);
    float* smBI = (float*)(smem + SM_BI);

    int tid = threadIdx.x;
    int wid = tid >> 5, lane = tid & 31;
    int gid = lane >> 2, tig = lane & 3;
    int cell = cell_base + blockIdx.y;
    const float* x = use_fb ? (blockIdx.y == 0 ? d_xs : d_xc)
                            : (blockIdx.y == 0 ? x0 : x1);
    const __half* hin = use_comb ? d_h0c : d_hbuf[cell][rd];
    const float*  cin = use_comb ? d_c0c : d_cbuf[cell];
    __half* hout = d_hbuf[cell][rd ^ 1];
    float*  cout = d_cbuf[cell];
    const float* Wh = d_W4h[cell];
    int nt = blockIdx.x;
    int col0 = nt << 7;
    int m_lo = (blockIdx.z * 128) / MSPLIT;
    int m_hi = ((blockIdx.z + 1) * 128) / MSPLIT;

    int r = tid >> 1, half = tid & 1;

    // ---- load resident weight tile (fp32 -> half2), Wi, bias ----
    {
        const float* wrow = Wh + (size_t)(col0 + r) * 256 + half * 16;
        #pragma unroll
        for (int c = 0; c < 8; c++) {
            const float* src = wrow + c * 32;
            uint32_t w[8];
            #pragma unroll
            for (int j = 0; j < 8; j++) {
                __half2 h2 = __floats2half2_rn(src[2 * j], src[2 * j + 1]);
                w[j] = *(uint32_t*)&h2;
            }
            uint32_t* dst = smB + ((size_t)c * 128 + r) * AW + half * 8;
            *(uint4*)(dst)     = make_uint4(w[0], w[1], w[2], w[3]);
            *(uint4*)(dst + 4) = make_uint4(w[4], w[5], w[6], w[7]);
        }
        if (tid < 128)
            *(float4*)(smWI + tid * 4) = *(const float4*)(d_W4i[cell] + (size_t)(col0 + tid) * 4);
        if (tid < 32)
            *(float4*)(smBI + tid * 4) = *(const float4*)(d_b4[cell] + col0 + tid * 4);
    }
    __syncthreads();

    // quarter-epilogue of a finished mtile (j = quarter index 0..3)
    auto epi_quarter = [&](const uint32_t (&acc)[16][2], int j, int row0) {
        #pragma unroll
        for (int rr = 0; rr < 2; rr++) {
            int row = row0 + wid * 16 + gid + rr * 8;
            float xv[4];
            #pragma unroll
            for (int s = 0; s < 4; s++) xv[s] = x[(size_t)row * xstride + s];
            int ub = 8 * j + 2 * tig;
            size_t cb = (size_t)row * HID + nt * 32 + ub;
            float2 cold = *(const float2*)(cin + cb);
            float2 vi = __half22float2(H2(acc[j     ][rr]));
            float2 vf = __half22float2(H2(acc[j +  4][rr]));
            float2 vg = __half22float2(H2(acc[j +  8][rr]));
            float2 vo = __half22float2(H2(acc[j + 12][rr]));
            float hv[2], cv[2];
            #pragma unroll
            for (int e = 0; e < 2; e++) {
                int u = ub + e;
                float g_i = (e == 0 ? vi.x : vi.y) + smBI[u];
                float g_f = (e == 0 ? vf.x : vf.y) + smBI[32 + u];
                float g_g = (e == 0 ? vg.x : vg.y) + smBI[64 + u];
                float g_o = (e == 0 ? vo.x : vo.y) + smBI[96 + u];
                #pragma unroll
                for (int s = 0; s < 4; s++) {
                    g_i = fmaf(smWI[u * 4 + s],        xv[s], g_i);
                    g_f = fmaf(smWI[(32 + u) * 4 + s], xv[s], g_f);
                    g_g = fmaf(smWI[(64 + u) * 4 + s], xv[s], g_g);
                    g_o = fmaf(smWI[(96 + u) * 4 + s], xv[s], g_o);
                }
                float co = (e == 0) ? cold.x : cold.y;
                float cn = fmaf(sig_fast(gclamp(g_f)), co,
                                sig_fast(gclamp(g_i)) * tanh_fast(gclamp(g_g)));
                float hn = sig_fast(gclamp(g_o)) * tanh_fast(gclamp(cn));
                cv[e] = cn; hv[e] = hn;
            }
            *(float2*)(cout + cb) = make_float2(cv[0], cv[1]);
            *(__half2*)(hout + cb) = __floats2half2_rn(hv[0], hv[1]);
        }
    };

    // one mtile: stage+mma into accC; interleave quarter-epis of accP
    uint4 va0, va1;
    {
        const uint4* arow = (const uint4*)(hin + (size_t)((m_lo << 7) + r) * 256 + half * 16);
        va0 = arow[0]; va1 = arow[1];
    }

    auto mtile_pass = [&](uint32_t (&accC)[16][2], const uint32_t (&accP)[16][2],
                          int doEpi, int row0C, int row0P, int pfNext) {
        const uint4* arow = (const uint4*)(hin + (size_t)(row0C + r) * 256 + half * 16);
        #pragma unroll
        for (int i = 0; i < 16; i++) { accC[i][0] = 0u; accC[i][1] = 0u; }

        for (int c = 0; c < 8; c++) {
            uint32_t* dst = smA + (size_t)((c & 1) * 128 + r) * AW + half * 8;
            *(uint4*)(dst)     = va0;
            *(uint4*)(dst + 4) = va1;
            // prefetch next chunk (or next mtile's chunk 0) BEFORE the barrier
            if (c < 7) {
                va0 = arow[(c + 1) * 4 + 0];
                va1 = arow[(c + 1) * 4 + 1];
            } else if (pfNext) {
                const uint4* arow2 = (const uint4*)(hin + (size_t)(row0C + 128 + r) * 256 + half * 16);
                va0 = arow2[0]; va1 = arow2[1];
            }
            __syncthreads();
            const uint32_t* Ab = smA + (size_t)((c & 1) * 128 + wid * 16) * AW;
            const uint32_t* Bb = smB + (size_t)c * 128 * AW;
            #pragma unroll
            for (int s = 0; s < 2; s++) {
                int kk = s * 8;
                uint32_t a0 = Ab[(size_t)gid * AW + kk + tig];
                uint32_t a1 = Ab[(size_t)(gid + 8) * AW + kk + tig];
                uint32_t a2 = Ab[(size_t)gid * AW + kk + tig + 4];
                uint32_t a3 = Ab[(size_t)(gid + 8) * AW + kk + tig + 4];
                #pragma unroll
                for (int n8 = 0; n8 < 16; n8++) {
                    uint32_t b0 = Bb[(size_t)(n8 * 8 + gid) * AW + kk + tig];
                    uint32_t b1 = Bb[(size_t)(n8 * 8 + gid) * AW + kk + tig + 4];
                    mma_f16acc(accC[n8], a0, a1, a2, a3, b0, b1);
                }
            }
            // interleaved epilogue of previous mtile (quarters on chunks 0..3)
            if (doEpi && c < 4) epi_quarter(accP, c, row0P);
        }
    };

    uint32_t accA[16][2], accB[16][2];
    int nmt = m_hi - m_lo;
    for (int i = 0; i < nmt; i += 2) {
        int row0 = (m_lo + i) << 7;
        mtile_pass(accA, accB, i > 0, row0, row0 - 128, (i + 1 < nmt));
        if (i + 1 < nmt)
            mtile_pass(accB, accA, 1, row0 + 128, row0, (i + 2 < nmt));
    }
    // drain: epilogue of the last mtile
    {
        int lastRow0 = (m_hi - 1) << 7;
        if (nmt & 1) {
            #pragma unroll
            for (int j = 0; j < 4; j++) epi_quarter(accA, j, lastRow0);
        } else {
            #pragma unroll
            for (int j = 0; j < 4; j++) epi_quarter(accB, j, lastRow0);
        }
    }
}

// ---------------- combine encoder finals ----------------
__global__ void combine_kernel() {
    size_t i = (size_t)blockIdx.x * blockDim.x + threadIdx.x;
    float4 c0 = ((const float4*)d_cbuf[0])[i];
    float4 c1 = ((const float4*)d_cbuf[1])[i];
    ((float4*)d_c0c)[i] = make_float4(c0.x + c1.x, c0.y + c1.y, c0.z + c1.z, c0.w + c1.w);
    const __half2* ha = (const __half2*)d_hbuf[0][0];
    const __half2* hb = (const __half2*)d_hbuf[1][0];
    __half2* ho = (__half2*)d_h0c;
    #pragma unroll
    for (int j = 0; j < 2; j++) {
        float2 a = __half22float2(ha[2 * i + j]);
        float2 b = __half22float2(hb[2 * i + j]);
        ho[2 * i + j] = __floats2half2_rn(a.x + b.x, a.y + b.y);
    }
}

// ---------------- decoder heads ----------------
__global__ void heads_kernel(int t, int parity,
    const float* __restrict__ fsw, const float* __restrict__ fsb,
    const float* __restrict__ fcw, const float* __restrict__ fcb,
    const float* __restrict__ ew,  const float* __restrict__ eb,
    float* __restrict__ out)
{
    int gtid = blockIdx.x * blockDim.x + threadIdx.x;
    int row  = gtid >> 5;
    int lane = gtid & 31;
    if (row >= NB) return;
    const __half* hs = d_hbuf[2][parity] + (size_t)row * HID;
    const __half* hc = d_hbuf[3][parity] + (size_t)row * HID;
    float vs[8], vc[8];
    #pragma unroll
    for (int i = 0; i < 8; i++) {
        vs[i] = __half2float(hs[lane + 32 * i]);
        vc[i] = __half2float(hc[lane + 32 * i]);
    }

    float r[10];
    #pragma unroll
    for (int o = 0; o < 4; o++) {
        float p = 0.f;
        #pragma unroll
        for (int i = 0; i < 8; i++) p = fmaf(fsw[o * 256 + lane + 32 * i], vs[i], p);
        r[o] = p;
    }
    #pragma unroll
    for (int o = 0; o < 2; o++) {
        float p = 0.f;
        #pragma unroll
        for (int i = 0; i < 8; i++) p = fmaf(fcw[o * 256 + lane + 32 * i], vc[i], p);
        r[4 + o] = p;
    }
    #pragma unroll
    for (int o = 0; o < 4; o++) {
        float p = 0.f;
        #pragma unroll
        for (int i = 0; i < 8; i++) p = fmaf(ew[o * 256 + lane + 32 * i], vc[i], p);
        r[6 + o] = p;
    }
    #pragma unroll
    for (int off = 16; off > 0; off >>= 1)
        #pragma unroll
        for (int o = 0; o < 10; o++) r[o] += __shfl_xor_sync(0xffffffffu, r[o], off);

    if (lane == 0) {
        #pragma unroll
        for (int s = 0; s < 4; s++) {
            float v = r[s] + fsb[s];
            v = fminf(fmaxf(v, -100.f), 100.f);
            out[(size_t)row * 64 + t * 4 + s] = v;
            d_xs[row * 4 + s] = v;
        }
        float l0 = fmaxf(r[4] + fcb[0], 0.f);
        float l1 = fmaxf(r[5] + fcb[1], 0.f);
        float m  = fmaxf(l0, l1);
        float e0 = expf(l0 - m), e1 = expf(l1 - m);
        float inv = 1.f / (e0 + e1);
        size_t cb = (size_t)NB * 64;
        out[cb + (size_t)row * 32 + t * 2 + 0] = e0 * inv;
        out[cb + (size_t)row * 32 + t * 2 + 1] = e1 * inv;
        #pragma unroll
        for (int s = 0; s < 4; s++) d_xc[row * 4 + s] = fmaxf(r[6 + s] + eb[s], 0.f);
    }
}

// ---------------- host ----------------
extern "C" void kernel_launch(void* const* d_in, const int* in_sizes, int n_in,
                              void* d_out, int out_size)
{
    (void)in_sizes; (void)n_in; (void)out_size;
    const float* speed = (const float*)d_in[0];
    const float* pos   = (const float*)d_in[1];

    cudaFuncSetAttribute(cell_mma_kernel, cudaFuncAttributeMaxDynamicSharedMemorySize, SM_TOTAL);

    for (int cell = 0; cell < 4; cell++) {
        int base = 2 + 4 * cell;
        prep_kernel<<<1024, 256>>>(cell,
            (const float*)d_in[base + 1],
            (const float*)d_in[base + 0],
            (const float*)d_in[base + 2],
            (const float*)d_in[base + 3]);
    }

    dim3 tgrid(8, 2, MSPLIT);

    // ---- encoders ----
    cell_first_kernel<<<dim3(8, 128, 2), 256>>>(speed, pos, 64);
    for (int t = 1; t < 16; t++)
        cell_mma_kernel<<<tgrid, 256, SM_TOTAL>>>(0, speed + 4 * t, pos + 4 * t, 64, t & 1, 0, 0);

    combine_kernel<<<4096, 256>>>();

    // ---- decoders ----
    const float* fsw = (const float*)d_in[18];
    const float* fsb = (const float*)d_in[19];
    const float* fcw = (const float*)d_in[20];
    const float* fcb = (const float*)d_in[21];
    const float* ew  = (const float*)d_in[22];
    const float* eb  = (const float*)d_in[23];
    float* out = (float*)d_out;

    for (int t = 0; t < TOUT; t++) {
        if (t == 0)
            cell_mma_kernel<<<tgrid, 256, SM_TOTAL>>>(2, speed + 60, pos + 60, 64, 0, 1, 0);
        else
            cell_mma_kernel<<<tgrid, 256, SM_TOTAL>>>(2, nullptr, nullptr, 4, t & 1, 0, 1);
        heads_kernel<<<2048, 256>>>(t, (t & 1) ^ 1, fsw, fsb, fcw, fcb, ew, eb, out);
    }
}

// round 14
// speedup vs baseline: 2.6062x; 1.5822x over previous
#include <cuda_runtime.h>
#include <cuda_fp16.h>
#include <math.h>
#include <stdint.h>

#define NB   16384
#define HID  256
#define TOUT 16
#define MSPLIT 9

// ---------------- persistent device scratch ----------------
__device__ float  d_W4h[4][1024 * 256];   // permuted recurrent weights [col'][k] (fp32)
__device__ float  d_W4i[4][1024 * 4];
__device__ float  d_b4 [4][1024];
__device__ __half d_hbuf[4][2][NB * HID]; // hidden state, fp16
__device__ float  d_cbuf[4][NB * HID];    // cell state, fp32
__device__ __half d_h0c[NB * HID];
__device__ float  d_c0c[NB * HID];
__device__ float  d_xs[NB * 4];
__device__ float  d_xc[NB * 4];

__device__ __forceinline__ float sigf(float x) { return 1.0f / (1.0f + expf(-x)); }
__device__ __forceinline__ float sig_fast(float x) {
    float e = __expf(-x);
    return __fdividef(1.0f, 1.0f + e);
}
__device__ __forceinline__ float tanh_fast(float x) {
    float e = __expf(-2.0f * x);
    return (1.0f - e) * __fdividef(1.0f, 1.0f + e);
}
__device__ __forceinline__ float gclamp(float x) { return fminf(fmaxf(x, -30.0f), 30.0f); }

__device__ __forceinline__ void mma_f16acc(uint32_t* d,
    uint32_t a0, uint32_t a1, uint32_t a2, uint32_t a3, uint32_t b0, uint32_t b1) {
    asm volatile("mma.sync.aligned.m16n8k16.row.col.f16.f16.f16.f16 "
        "{%0,%1}, {%2,%3,%4,%5}, {%6,%7}, {%0,%1};"
        : "+r"(d[0]), "+r"(d[1])
        : "r"(a0), "r"(a1), "r"(a2), "r"(a3), "r"(b0), "r"(b1));
}

__device__ __forceinline__ __half2 H2(uint32_t u) { return *(__half2*)&u; }

// ---------------- SMEM layout ----------------
// 64-half chunks: 32 data words + 4 pad per row per chunk
#define AW 36
#define SM_WI   0                         // 128*4 floats = 2048 B
#define SM_BI   2048                      // 512 B
#define SM_A    2560                      // 2*128*36*4  = 36864 B
#define SM_B    39424                     // 4*128*36*4  = 73728 B
#define SM_TOTAL 113152

// ---------------- weight permutation ----------------
__global__ void prep_kernel(int cell,
                            const float* __restrict__ Whh,
                            const float* __restrict__ Wih,
                            const float* __restrict__ bih,
                            const float* __restrict__ bhh) {
    int colp = blockIdx.x;
    int k    = threadIdx.x;
    int g    = (colp & 127) >> 5;
    int u    = ((colp >> 7) << 5) + (colp & 31);
    int orig = g * 256 + u;
    d_W4h[cell][colp * 256 + k] = Whh[orig * 256 + k];
    if (k < 4) d_W4i[cell][colp * 4 + k] = Wih[orig * 4 + k];
    if (k == 0) d_b4[cell][colp] = bih[orig] + bhh[orig];
}

// ---------------- first step (h=c=0) ----------------
__global__ __launch_bounds__(256, 2) void cell_first_kernel(
    const float* __restrict__ x0, const float* __restrict__ x1, int xstride)
{
    int cell = blockIdx.z;
    const float* x = blockIdx.z == 0 ? x0 : x1;
    __half* hout = d_hbuf[cell][1];
    float*  cout = d_cbuf[cell];
    int row0 = blockIdx.y << 7;
    int col0 = blockIdx.x << 7;
    int tx = threadIdx.x & 15;
    int ty = threadIdx.x >> 4;

    float xv[8][4];
    #pragma unroll
    for (int rr = 0; rr < 8; rr++) {
        int row = row0 + (ty << 3) + rr;
        #pragma unroll
        for (int s = 0; s < 4; s++) xv[rr][s] = x[(size_t)row * xstride + s];
    }
    const float* Wi = d_W4i[cell];
    const float* bb = d_b4[cell];
    int ubase = blockIdx.x << 5;

    #pragma unroll
    for (int hh = 0; hh < 2; hh++) {
        int u = ubase + tx + (hh << 4);
        float wi[4][4], bg[4];
        #pragma unroll
        for (int g = 0; g < 4; g++) {
            int colp = col0 + (g << 5) + tx + (hh << 4);
            bg[g] = bb[colp];
            #pragma unroll
            for (int s = 0; s < 4; s++) wi[g][s] = Wi[colp * 4 + s];
        }
        #pragma unroll
        for (int rr = 0; rr < 8; rr++) {
            int row = row0 + (ty << 3) + rr;
            float gt[4];
            #pragma unroll
            for (int g = 0; g < 4; g++) {
                float v = bg[g];
                #pragma unroll
                for (int s = 0; s < 4; s++) v = fmaf(wi[g][s], xv[rr][s], v);
                gt[g] = v;
            }
            float ig = sigf(gt[0]);
            float gg = tanhf(gt[2]);
            float og = sigf(gt[3]);
            float cn = ig * gg;
            float hn = og * tanhf(cn);
            cout[(size_t)row * HID + u] = cn;
            hout[(size_t)row * HID + u] = __float2half(hn);
        }
    }
}

// ---------------- fp16 mma.sync LSTM step (64-half chunks, 4 syncs/mtile) ----------------
// grid (8 N-tiles, 2 cells, MSPLIT M-groups), 256 threads = 8 warps.
__global__ __launch_bounds__(256, 1) void cell_mma_kernel(
    int cell_base, const float* __restrict__ x0, const float* __restrict__ x1,
    int xstride, int rd, int use_comb, int use_fb)
{
    extern __shared__ char smem[];
    uint32_t* smA = (uint32_t*)(smem + SM_A);   // [2][128][AW]
    uint32_t* smB = (uint32_t*)(smem + SM_B);   // [4][128][AW]
    float* smWI = (float*)(smem + SM_WI);
    float* smBI = (float*)(smem + SM_BI);

    int tid = threadIdx.x;
    int wid = tid >> 5, lane = tid & 31;
    int gid = lane >> 2, tig = lane & 3;
    int cell = cell_base + blockIdx.y;
    const float* x = use_fb ? (blockIdx.y == 0 ? d_xs : d_xc)
                            : (blockIdx.y == 0 ? x0 : x1);
    const __half* hin = use_comb ? d_h0c : d_hbuf[cell][rd];
    const float*  cin = use_comb ? d_c0c : d_cbuf[cell];
    __half* hout = d_hbuf[cell][rd ^ 1];
    float*  cout = d_cbuf[cell];
    const float* Wh = d_W4h[cell];
    int nt = blockIdx.x;
    int col0 = nt << 7;
    int m_lo = (blockIdx.z * 128) / MSPLIT;
    int m_hi = ((blockIdx.z + 1) * 128) / MSPLIT;

    int r = tid >> 1, half = tid & 1;

    // ---- load resident weight tile (fp32 -> half2), Wi, bias ----
    {
        const float* wrow = Wh + (size_t)(col0 + r) * 256;
        #pragma unroll
        for (int c = 0; c < 4; c++) {
            const float* src = wrow + c * 64 + half * 32;
            uint32_t w[16];
            #pragma unroll
            for (int j = 0; j < 16; j++) {
                __half2 h2 = __floats2half2_rn(src[2 * j], src[2 * j + 1]);
                w[j] = *(uint32_t*)&h2;
            }
            uint32_t* dst = smB + ((size_t)c * 128 + r) * AW + half * 16;
            *(uint4*)(dst)      = make_uint4(w[0],  w[1],  w[2],  w[3]);
            *(uint4*)(dst + 4)  = make_uint4(w[4],  w[5],  w[6],  w[7]);
            *(uint4*)(dst + 8)  = make_uint4(w[8],  w[9],  w[10], w[11]);
            *(uint4*)(dst + 12) = make_uint4(w[12], w[13], w[14], w[15]);
        }
        if (tid < 128)
            *(float4*)(smWI + tid * 4) = *(const float4*)(d_W4i[cell] + (size_t)(col0 + tid) * 4);
        if (tid < 32)
            *(float4*)(smBI + tid * 4) = *(const float4*)(d_b4[cell] + col0 + tid * 4);
    }
    __syncthreads();

    // prologue: preload chunk 0 of first mtile (4 uint4 = 32 halves per thread)
    uint4 va[4];
    {
        const uint4* arow = (const uint4*)(hin + (size_t)((m_lo << 7) + r) * 256);
        #pragma unroll
        for (int j = 0; j < 4; j++) va[j] = arow[half * 4 + j];
    }

    for (int mt = m_lo; mt < m_hi; mt++) {
        int row0 = mt << 7;
        const uint4* arow = (const uint4*)(hin + (size_t)(row0 + r) * 256);

        uint32_t acc[16][2];
        #pragma unroll
        for (int i = 0; i < 16; i++) { acc[i][0] = 0u; acc[i][1] = 0u; }

        #pragma unroll
        for (int c = 0; c < 4; c++) {
            // stage current chunk
            uint32_t* dst = smA + (size_t)((c & 1) * 128 + r) * AW + half * 16;
            *(uint4*)(dst)      = va[0];
            *(uint4*)(dst + 4)  = va[1];
            *(uint4*)(dst + 8)  = va[2];
            *(uint4*)(dst + 12) = va[3];
            // prefetch next chunk BEFORE the barrier
            if (c < 3) {
                #pragma unroll
                for (int j = 0; j < 4; j++) va[j] = arow[(c + 1) * 8 + half * 4 + j];
            } else if (mt + 1 < m_hi) {
                const uint4* arow2 = (const uint4*)(hin + (size_t)(row0 + 128 + r) * 256);
                #pragma unroll
                for (int j = 0; j < 4; j++) va[j] = arow2[half * 4 + j];
            }
            __syncthreads();
            const uint32_t* Ab = smA + (size_t)((c & 1) * 128 + wid * 16) * AW;
            const uint32_t* Bb = smB + (size_t)c * 128 * AW;
            #pragma unroll
            for (int s = 0; s < 4; s++) {
                int kk = s * 8;
                uint32_t a0 = Ab[(size_t)gid * AW + kk + tig];
                uint32_t a1 = Ab[(size_t)(gid + 8) * AW + kk + tig];
                uint32_t a2 = Ab[(size_t)gid * AW + kk + tig + 4];
                uint32_t a3 = Ab[(size_t)(gid + 8) * AW + kk + tig + 4];
                #pragma unroll
                for (int n8 = 0; n8 < 16; n8++) {
                    uint32_t b0 = Bb[(size_t)(n8 * 8 + gid) * AW + kk + tig];
                    uint32_t b1 = Bb[(size_t)(n8 * 8 + gid) * AW + kk + tig + 4];
                    mma_f16acc(acc[n8], a0, a1, a2, a3, b0, b1);
                }
            }
        }

        // ---- fused LSTM epilogue (fast activations) ----
        #pragma unroll
        for (int rr = 0; rr < 2; rr++) {
            int row = row0 + wid * 16 + gid + rr * 8;
            float xv[4];
            #pragma unroll
            for (int s = 0; s < 4; s++) xv[s] = x[(size_t)row * xstride + s];
            #pragma unroll
            for (int j = 0; j < 4; j++) {
                int ub = 8 * j + 2 * tig;
                float2 cold = *(const float2*)(cin + (size_t)row * HID + nt * 32 + ub);
                float2 vi = __half22float2(H2(acc[j     ][rr]));
                float2 vf = __half22float2(H2(acc[j +  4][rr]));
                float2 vg = __half22float2(H2(acc[j +  8][rr]));
                float2 vo = __half22float2(H2(acc[j + 12][rr]));
                float hv[2], cv[2];
                #pragma unroll
                for (int e = 0; e < 2; e++) {
                    int u = ub + e;
                    float g_i = (e == 0 ? vi.x : vi.y) + smBI[u];
                    float g_f = (e == 0 ? vf.x : vf.y) + smBI[32 + u];
                    float g_g = (e == 0 ? vg.x : vg.y) + smBI[64 + u];
                    float g_o = (e == 0 ? vo.x : vo.y) + smBI[96 + u];
                    #pragma unroll
                    for (int s = 0; s < 4; s++) {
                        g_i = fmaf(smWI[u * 4 + s],        xv[s], g_i);
                        g_f = fmaf(smWI[(32 + u) * 4 + s], xv[s], g_f);
                        g_g = fmaf(smWI[(64 + u) * 4 + s], xv[s], g_g);
                        g_o = fmaf(smWI[(96 + u) * 4 + s], xv[s], g_o);
                    }
                    float co = (e == 0) ? cold.x : cold.y;
                    float cn = fmaf(sig_fast(gclamp(g_f)), co,
                                    sig_fast(gclamp(g_i)) * tanh_fast(gclamp(g_g)));
                    float hn = sig_fast(gclamp(g_o)) * tanh_fast(gclamp(cn));
                    cv[e] = cn; hv[e] = hn;
                }
                *(float2*)(cout + (size_t)row * HID + nt * 32 + ub) = make_float2(cv[0], cv[1]);
                *(__half2*)(hout + (size_t)row * HID + nt * 32 + ub) = __floats2half2_rn(hv[0], hv[1]);
            }
        }
    }
}

// ---------------- combine encoder finals ----------------
__global__ void combine_kernel() {
    size_t i = (size_t)blockIdx.x * blockDim.x + threadIdx.x;
    float4 c0 = ((const float4*)d_cbuf[0])[i];
    float4 c1 = ((const float4*)d_cbuf[1])[i];
    ((float4*)d_c0c)[i] = make_float4(c0.x + c1.x, c0.y + c1.y, c0.z + c1.z, c0.w + c1.w);
    const __half2* ha = (const __half2*)d_hbuf[0][0];
    const __half2* hb = (const __half2*)d_hbuf[1][0];
    __half2* ho = (__half2*)d_h0c;
    #pragma unroll
    for (int j = 0; j < 2; j++) {
        float2 a = __half22float2(ha[2 * i + j]);
        float2 b = __half22float2(hb[2 * i + j]);
        ho[2 * i + j] = __floats2half2_rn(a.x + b.x, a.y + b.y);
    }
}

// ---------------- decoder heads ----------------
__global__ void heads_kernel(int t, int parity,
    const float* __restrict__ fsw, const float* __restrict__ fsb,
    const float* __restrict__ fcw, const float* __restrict__ fcb,
    const float* __restrict__ ew,  const float* __restrict__ eb,
    float* __restrict__ out)
{
    int gtid = blockIdx.x * blockDim.x + threadIdx.x;
    int row  = gtid >> 5;
    int lane = gtid & 31;
    if (row >= NB) return;
    const __half* hs = d_hbuf[2][parity] + (size_t)row * HID;
    const __half* hc = d_hbuf[3][parity] + (size_t)row * HID;
    float vs[8], vc[8];
    #pragma unroll
    for (int i = 0; i < 8; i++) {
        vs[i] = __half2float(hs[lane + 32 * i]);
        vc[i] = __half2float(hc[lane + 32 * i]);
    }

    float r[10];
    #pragma unroll
    for (int o = 0; o < 4; o++) {
        float p = 0.f;
        #pragma unroll
        for (int i = 0; i < 8; i++) p = fmaf(fsw[o * 256 + lane + 32 * i], vs[i], p);
        r[o] = p;
    }
    #pragma unroll
    for (int o = 0; o < 2; o++) {
        float p = 0.f;
        #pragma unroll
        for (int i = 0; i < 8; i++) p = fmaf(fcw[o * 256 + lane + 32 * i], vc[i], p);
        r[4 + o] = p;
    }
    #pragma unroll
    for (int o = 0; o < 4; o++) {
        float p = 0.f;
        #pragma unroll
        for (int i = 0; i < 8; i++) p = fmaf(ew[o * 256 + lane + 32 * i], vc[i], p);
        r[6 + o] = p;
    }
    #pragma unroll
    for (int off = 16; off > 0; off >>= 1)
        #pragma unroll
        for (int o = 0; o < 10; o++) r[o] += __shfl_xor_sync(0xffffffffu, r[o], off);

    if (lane == 0) {
        #pragma unroll
        for (int s = 0; s < 4; s++) {
            float v = r[s] + fsb[s];
            v = fminf(fmaxf(v, -100.f), 100.f);
            out[(size_t)row * 64 + t * 4 + s] = v;
            d_xs[row * 4 + s] = v;
        }
        float l0 = fmaxf(r[4] + fcb[0], 0.f);
        float l1 = fmaxf(r[5] + fcb[1], 0.f);
        float m  = fmaxf(l0, l1);
        float e0 = expf(l0 - m), e1 = expf(l1 - m);
        float inv = 1.f / (e0 + e1);
        size_t cb = (size_t)NB * 64;
        out[cb + (size_t)row * 32 + t * 2 + 0] = e0 * inv;
        out[cb + (size_t)row * 32 + t * 2 + 1] = e1 * inv;
        #pragma unroll
        for (int s = 0; s < 4; s++) d_xc[row * 4 + s] = fmaxf(r[6 + s] + eb[s], 0.f);
    }
}

// ---------------- host ----------------
extern "C" void kernel_launch(void* const* d_in, const int* in_sizes, int n_in,
                              void* d_out, int out_size)
{
    (void)in_sizes; (void)n_in; (void)out_size;
    const float* speed = (const float*)d_in[0];
    const float* pos   = (const float*)d_in[1];

    cudaFuncSetAttribute(cell_mma_kernel, cudaFuncAttributeMaxDynamicSharedMemorySize, SM_TOTAL);

    for (int cell = 0; cell < 4; cell++) {
        int base = 2 + 4 * cell;
        prep_kernel<<<1024, 256>>>(cell,
            (const float*)d_in[base + 1],
            (const float*)d_in[base + 0],
            (const float*)d_in[base + 2],
            (const float*)d_in[base + 3]);
    }

    dim3 tgrid(8, 2, MSPLIT);

    // ---- encoders ----
    cell_first_kernel<<<dim3(8, 128, 2), 256>>>(speed, pos, 64);
    for (int t = 1; t < 16; t++)
        cell_mma_kernel<<<tgrid, 256, SM_TOTAL>>>(0, speed + 4 * t, pos + 4 * t, 64, t & 1, 0, 0);

    combine_kernel<<<4096, 256>>>();

    // ---- decoders ----
    const float* fsw = (const float*)d_in[18];
    const float* fsb = (const float*)d_in[19];
    const float* fcw = (const float*)d_in[20];
    const float* fcb = (const float*)d_in[21];
    const float* ew  = (const float*)d_in[22];
    const float* eb  = (const float*)d_in[23];
    float* out = (float*)d_out;

    for (int t = 0; t < TOUT; t++) {
        if (t == 0)
            cell_mma_kernel<<<tgrid, 256, SM_TOTAL>>>(2, speed + 60, pos + 60, 64, 0, 1, 0);
        else
            cell_mma_kernel<<<tgrid, 256, SM_TOTAL>>>(2, nullptr, nullptr, 4, t & 1, 0, 1);
        heads_kernel<<<2048, 256>>>(t, (t & 1) ^ 1, fsw, fsb, fcw, fcb, ew, eb, out);
    }
}